// round 3
// baseline (speedup 1.0000x reference)
#include <cuda_runtime.h>
#include <cstdint>

#define NODES   64
#define NINPUT  16
#define NOUT    8
#define NEDGE   256
#define BATCH   8192
#define PASSES  64
#define G       16            // edge slots per chunk (lanes per column)
#define TB      128           // threads per block
#define CPB     8             // columns per block (TB / G * 2 cols per warp)
#define GRIDB   (BATCH / CPB) // 1024 blocks
#define MAXCH   257           // worst-case chunks + wrap chunk
#define STRIDE  65            // floats per column (64 nodes + scratch row 64)

__device__ uint2 g_recs[MAXCH * G + G];
__device__ int   g_nchunks;

// ---------------------------------------------------------------------------
// Scheduler: greedy list scheduling into chunks of G=16 pairwise hazard-free
// edges (RAW/WAW/WAR preserved wrt sequential order via footprint masks).
// Thread-0 scan over a 256-bit remaining bitmask (registers) + packed (s,d)
// in smem; warp-parallel record emission.
// rec.x = (dst_row_byte_off << 16) | src_row_byte_off,  rec.y = w * 2*log2(e)
// ---------------------------------------------------------------------------
__global__ void sched_kernel(const float* __restrict__ w,
                             const int*   __restrict__ src,
                             const int*   __restrict__ dst) {
    __shared__ unsigned short packed[NEDGE];
    __shared__ short ord[256 * G];
    __shared__ int   s_nch;
    const int lane = threadIdx.x;

    for (int e = lane; e < NEDGE; e += 32)
        packed[e] = (unsigned short)((dst[e] << 8) | src[e]);
    __syncwarp();

    if (lane == 0) {
        unsigned long long rem[4] = {~0ull, ~0ull, ~0ull, ~0ull};
        int total = 0, nch = 0;
        while (total < NEDGE) {
            unsigned long long Wm = 0ull, Rm = 0ull;
            int members = 0;
            for (int w0 = 0; w0 < 4 && members < G; w0++) {
                unsigned long long m = rem[w0];
                while (m && members < G) {
                    const int b = __ffsll((long long)m) - 1;
                    m &= m - 1;
                    const int e = (w0 << 6) + b;
                    const unsigned p = packed[e];
                    const int s = p & 255, d = p >> 8;
                    if (!((Wm >> s) & 1ull) && !((Wm >> d) & 1ull) &&
                        !((Rm >> d) & 1ull)) {
                        ord[nch * G + members] = (short)e;
                        rem[w0] &= ~(1ull << b);
                        members++; total++;
                    }
                    // footprint added for members AND skipped edges: preserves
                    // program order across skips, blocks in-chunk conflicts
                    Wm |= 1ull << d;
                    Rm |= 1ull << s;
                }
            }
            for (; members < G; members++) ord[nch * G + members] = -1;
            nch++;
        }
        s_nch = nch;
    }
    __syncwarp();

    const int nch = s_nch;
    const float K2 = 2.8853900817779268f;  // 2 * log2(e)
    // emit nch chunks + wrap chunk (copy of chunk 0) for prefetch wrap
    for (int idx = lane; idx < (nch + 1) * G; idx += 32) {
        const int e = ord[idx < nch * G ? idx : idx - nch * G];
        uint2 rec;
        if (e < 0) {
            rec.x = (256u << 16) | 256u;     // scratch row 64 byte offset
            rec.y = __float_as_uint(0.0f);   // tanh(0)=0 -> dst unchanged
        } else {
            const unsigned s = (unsigned)src[e], d = (unsigned)dst[e];
            rec.x = ((d * 4u) << 16) | (s * 4u);
            rec.y = __float_as_uint(w[e] * K2);
        }
        g_recs[idx] = rec;
    }
    if (lane == 0) g_nchunks = nch;
}

// ---------------------------------------------------------------------------
// Main kernel: warp = 2 columns x 16 edge slots. Node state [col][row] in
// smem, stride 65 floats (bank = (col+row) mod 32). Each lane handles one
// chunk edge-slot of its column; __syncwarp() between chunks orders smem.
// tanh(x) = 1 - 2/(exp2(x*2log2e)+1) via MUFU ex2/rcp (~1e-6 per-op error).
// ---------------------------------------------------------------------------
__global__ void __launch_bounds__(TB, 1)
net_kernel(const float* __restrict__ x, float* __restrict__ out) {
    __shared__ float vals[CPB * STRIDE];

    const int tid  = threadIdx.x;
    const int lane = tid & 31;
    const int wid  = tid >> 5;
    const int cl   = wid * 2 + (lane >> 4);  // local column 0..7
    const int slot = lane & 15;
    const int bc   = blockIdx.x * CPB;

    // init: inputs rows 0..15 (coalesced-ish), zeros rows 16..64
    for (int i = tid; i < CPB * NINPUT; i += TB) {
        const int r = i >> 3, c = i & 7;
        vals[c * STRIDE + r] = x[r * BATCH + bc + c];
    }
    for (int i = tid; i < CPB * (STRIDE - NINPUT); i += TB) {
        const int r = NINPUT + (i >> 3), c = i & 7;
        vals[c * STRIDE + r] = 0.0f;
    }
    __syncthreads();

    const int nch = g_nchunks;
    char* base = (char*)(vals + cl * STRIDE);

    uint2 rec = __ldg(&g_recs[slot]);
    #pragma unroll 1
    for (int p = 0; p < PASSES; p++) {
        #pragma unroll 2
        for (int c = 0; c < nch; c++) {
            const uint2 nxt = __ldg(&g_recs[(c + 1) * G + slot]);  // wrap=chunk0
            const unsigned sb = rec.x & 0xffffu;
            const unsigned db = rec.x >> 16;
            const float wv = __uint_as_float(rec.y);
            const float v  = *(const float*)(base + sb);
            const float t1 = *(const float*)(base + db) + 1.0f;
            const float a = v * wv;
            float ev;  asm("ex2.approx.f32 %0, %1;" : "=f"(ev) : "f"(a));
            float r2;  asm("rcp.approx.f32 %0, %1;" : "=f"(r2) : "f"(ev + 1.0f));
            *(float*)(base + db) = fmaf(-2.0f, r2, t1);  // pv + 1 - 2/(ev+1)
            rec = nxt;
            __syncwarp();
        }
    }
    __syncthreads();

    for (int i = tid; i < CPB * NOUT; i += TB) {
        const int r = i >> 3, c = i & 7;
        out[r * BATCH + bc + c] = tanhf(vals[c * STRIDE + NINPUT + r]);
    }
}

extern "C" void kernel_launch(void* const* d_in, const int* in_sizes, int n_in,
                              void* d_out, int out_size) {
    const float* x   = (const float*)d_in[0];
    const float* w   = (const float*)d_in[1];
    const int*   src = (const int*)d_in[2];
    const int*   dst = (const int*)d_in[3];
    (void)in_sizes; (void)n_in; (void)out_size;

    sched_kernel<<<1, 32>>>(w, src, dst);
    net_kernel<<<GRIDB, TB>>>(x, (float*)d_out);
}